// round 11
// baseline (speedup 1.0000x reference)
#include <cuda_runtime.h>
#include <cuda_fp16.h>
#include <cstdint>

#define NB 2
#define NN 384
#define TFv 22
#define POSv 32
#define TPROJv 33
#define CSv 256
#define CZv 128
#define LN_EPS 1e-5f
#define PI_F 3.14159265358979323846f

__device__ float g_table[2048 * CZv];
__device__ float g_eL[NB * NN * CZv];
__device__ float g_eR[NB * NN * CZv];
__device__ __half g_W1f[CZv * CZv], g_W2f[CZv * CZv];

// ---------------------------------------------------------------------------
// helpers
// ---------------------------------------------------------------------------
__device__ __forceinline__ uint32_t smem_u32(const void* p) {
    uint32_t a;
    asm("{ .reg .u64 t; cvta.to.shared.u64 t, %1; cvt.u32.u64 %0, t; }"
        : "=r"(a) : "l"(p));
    return a;
}
__device__ __forceinline__ uint32_t packh_hi2(float x0, float x1, float& r0, float& r1) {
    __half2 v = __floats2half2_rn(x0, x1);
    r0 = x0 - __half2float(__low2half(v));
    r1 = x1 - __half2float(__high2half(v));
    return *reinterpret_cast<uint32_t*>(&v);
}
__device__ __forceinline__ uint32_t packh2(float r0, float r1) {
    __half2 v = __floats2half2_rn(r0, r1);
    return *reinterpret_cast<uint32_t*>(&v);
}
__device__ __forceinline__ void mma16816(float* c, uint32_t a0, uint32_t a1,
                                         uint32_t a2, uint32_t a3,
                                         uint32_t b0, uint32_t b1) {
    asm volatile(
        "mma.sync.aligned.m16n8k16.row.col.f32.f16.f16.f32 "
        "{%0,%1,%2,%3}, {%4,%5,%6,%7}, {%8,%9}, {%0,%1,%2,%3};"
        : "+f"(c[0]), "+f"(c[1]), "+f"(c[2]), "+f"(c[3])
        : "r"(a0), "r"(a1), "r"(a2), "r"(a3), "r"(b0), "r"(b1));
}
__device__ __forceinline__ void ldsm_x4(uint32_t& r0, uint32_t& r1,
                                        uint32_t& r2, uint32_t& r3, uint32_t addr) {
    asm volatile("ldmatrix.sync.aligned.m8n8.x4.shared.b16 {%0,%1,%2,%3}, [%4];"
                 : "=r"(r0), "=r"(r1), "=r"(r2), "=r"(r3) : "r"(addr));
}
__device__ __forceinline__ void stsm_x4(uint32_t addr, uint32_t r0, uint32_t r1,
                                        uint32_t r2, uint32_t r3) {
    asm volatile("stmatrix.sync.aligned.m8n8.x4.shared.b16 [%0], {%1,%2,%3,%4};"
                 :: "r"(addr), "r"(r0), "r"(r1), "r"(r2), "r"(r3) : "memory");
}

// ---------------------------------------------------------------------------
// Fused setup kernel (unchanged from R10 — correctness proven).
// ---------------------------------------------------------------------------
#define NR 8
#define TBLK 1024
#define NODEB (NB * NN / NR)   // 96

__global__ __launch_bounds__(256) void setup_kernel(
    const int* __restrict__ seq_idx, const float* __restrict__ seq_feat,
    const float* __restrict__ timestep, const float* __restrict__ frame_mask,
    const float* __restrict__ W_npos, const float* __restrict__ b_npos,
    const float* __restrict__ W_ntf, const float* __restrict__ b_ntf,
    const float* __restrict__ W_ntime, const float* __restrict__ b_ntime,
    const float* __restrict__ W_n1, const float* __restrict__ b_n1,
    const float* __restrict__ W_n2, const float* __restrict__ b_n2,
    const float* __restrict__ g_n, const float* __restrict__ be_n,
    const float* __restrict__ W_epos, const float* __restrict__ b_epos,
    const float* __restrict__ b_etf, const float* __restrict__ b_etime,
    const float* __restrict__ W_etf, const float* __restrict__ W_etime,
    const float* __restrict__ W_e1, const float* __restrict__ W_e2,
    float* __restrict__ out_seq) {
    __shared__ float su[4352];
    const int tid = threadIdx.x;
    const int bid = blockIdx.x;

    if (bid < TBLK) {
        float* sWe = su;
        float* emb = su + 4224;
        const int half = tid >> 7, c = tid & 127;
        for (int m = tid; m < CZv * POSv; m += 256)
            sWe[(m >> 5) * 33 + (m & 31)] = W_epos[m];
        const int relv = bid * 2 + half - 1000;
        if (c < 16) {
            float p = powf(2056.0f, (float)c * (1.0f / 16.0f));
            float ang = ((float)relv * PI_F) / p;
            emb[half * 32 + c] = sinf(ang);
            emb[half * 32 + c + 16] = cosf(ang);
        }
        __syncthreads();
        float acc = b_epos[c] + b_etf[c] + b_etime[c];
#pragma unroll
        for (int k = 0; k < POSv; k++) acc += emb[half * 32 + k] * sWe[c * 33 + k];
        g_table[(bid * 2 + half) * CZv + c] = acc;
        return;
    }
    if (bid >= TBLK + NODEB) {
        int t = (bid - TBLK - NODEB) * 256 + tid;
        g_W1f[t] = __float2half_rn(W_e1[t]);
        g_W2f[t] = __float2half_rn(W_e2[t]);
        return;
    }

    float (*spemb)[POSv] = (float(*)[POSv])su;
    float (*stemb)[36] = (float(*)[36])(su + 256);
    float (*sfeat)[24] = (float(*)[24])(su + 544);
    float (*sx)[CSv] = (float(*)[CSv])(su + 736);
    const int row0 = (bid - TBLK) * NR;

    {
        const int r = tid >> 5, j = tid & 31;
        const int row = row0 + r;
        const int b = row / NN;
        if (j < TFv) sfeat[r][j] = seq_feat[row * TFv + j];
        if (j < 16) {
            float p = powf(2056.0f, (float)j * (1.0f / 16.0f));
            float ang = ((float)seq_idx[row] * PI_F) / p;
            spemb[r][j] = sinf(ang);
            spemb[r][j + 16] = cosf(ang);
            float fm = frame_mask[row];
            float tt = timestep[b] * fm;
            float fr = expf(-0.6140226914650789f * (float)j);
            float a2 = tt * fr;
            stemb[r][j] = sinf(a2);
            stemb[r][j + 16] = cosf(a2);
            if (j == 0) stemb[r][32] = fm;
        }
    }
    __syncthreads();

    const int c = tid;
    float acc[NR];
    {
        float base = b_npos[c] + b_ntf[c] + b_ntime[c];
#pragma unroll
        for (int r = 0; r < NR; r++) acc[r] = base;
    }
#pragma unroll
    for (int k = 0; k < POSv; k++) {
        float wv = W_npos[c * POSv + k];
#pragma unroll
        for (int r = 0; r < NR; r++) acc[r] += spemb[r][k] * wv;
    }
#pragma unroll
    for (int k = 0; k < TFv; k++) {
        float wv = W_ntf[c * TFv + k];
#pragma unroll
        for (int r = 0; r < NR; r++) acc[r] += sfeat[r][k] * wv;
    }
#pragma unroll
    for (int k = 0; k < TPROJv; k++) {
        float wv = W_ntime[c * TPROJv + k];
#pragma unroll
        for (int r = 0; r < NR; r++) acc[r] += stemb[r][k] * wv;
    }
#pragma unroll
    for (int r = 0; r < NR; r++) sx[r][c] = fmaxf(acc[r], 0.0f);

    {
        const int c2 = tid & 127, half = tid >> 7;
        float e[NR];
#pragma unroll
        for (int r = 0; r < NR; r++) e[r] = 0.0f;
#pragma unroll
        for (int k = 0; k < TFv; k++) {
            float wv = W_etf[c2 * (2 * TFv) + half * TFv + k];
#pragma unroll
            for (int r = 0; r < NR; r++) e[r] += sfeat[r][k] * wv;
        }
#pragma unroll
        for (int k = 0; k < TPROJv; k++) {
            float wv = W_etime[c2 * (2 * TPROJv) + half * TPROJv + k];
#pragma unroll
            for (int r = 0; r < NR; r++) e[r] += stemb[r][k] * wv;
        }
        float* dst = half ? g_eR : g_eL;
#pragma unroll
        for (int r = 0; r < NR; r++) dst[(row0 + r) * CZv + c2] = e[r];
    }
    __syncthreads();

    float h[NR];
#pragma unroll
    for (int r = 0; r < NR; r++) h[r] = b_n1[c];
    {
        const float4* W1r = (const float4*)(W_n1 + c * CSv);
#pragma unroll 4
        for (int q = 0; q < CSv / 4; q++) {
            float4 wv = W1r[q];
#pragma unroll
            for (int r = 0; r < NR; r++) {
                float4 xv = *(const float4*)&sx[r][q * 4];
                h[r] += xv.x * wv.x + xv.y * wv.y + xv.z * wv.z + xv.w * wv.w;
            }
        }
    }
    __syncthreads();
#pragma unroll
    for (int r = 0; r < NR; r++) sx[r][c] = fmaxf(h[r], 0.0f);
    __syncthreads();

    float o[NR];
#pragma unroll
    for (int r = 0; r < NR; r++) o[r] = b_n2[c];
    {
        const float4* W2r = (const float4*)(W_n2 + c * CSv);
#pragma unroll 4
        for (int q = 0; q < CSv / 4; q++) {
            float4 wv = W2r[q];
#pragma unroll
            for (int r = 0; r < NR; r++) {
                float4 xv = *(const float4*)&sx[r][q * 4];
                o[r] += xv.x * wv.x + xv.y * wv.y + xv.z * wv.z + xv.w * wv.w;
            }
        }
    }
    __syncthreads();
#pragma unroll
    for (int r = 0; r < NR; r++) sx[r][c] = o[r];
    __syncthreads();

    {
        const int w = tid >> 5, l = tid & 31;
        float v[8];
#pragma unroll
        for (int g = 0; g < 8; g++) v[g] = sx[w][g * 32 + l];
        float s = 0.0f;
#pragma unroll
        for (int g = 0; g < 8; g++) s += v[g];
#pragma unroll
        for (int off = 16; off > 0; off >>= 1) s += __shfl_xor_sync(0xffffffffu, s, off);
        float mean = s * (1.0f / 256.0f);
        float sq = 0.0f;
#pragma unroll
        for (int g = 0; g < 8; g++) { float d = v[g] - mean; sq += d * d; }
#pragma unroll
        for (int off = 16; off > 0; off >>= 1) sq += __shfl_xor_sync(0xffffffffu, sq, off);
        float rstd = rsqrtf(sq * (1.0f / 256.0f) + LN_EPS);
        const int row = row0 + w;
#pragma unroll
        for (int g = 0; g < 8; g++) {
            int cc = g * 32 + l;
            out_seq[row * CSv + cc] = (v[g] - mean) * rstd * g_n[cc] + be_n[cc];
        }
    }
}

// ---------------------------------------------------------------------------
// Edge kernel: fp16x2 GEMMs, software-pipelined k-loop (double-buffered
// fragments: B1 issued before half0 MMAs; next-kk A/B0 between MMA halves).
// ---------------------------------------------------------------------------
#define WSTR 68
#define XH_W 0
#define XL_W (128 * WSTR)
#define WS_W (2 * 128 * WSTR)
#define REL_W (3 * 128 * WSTR)
#define EDGE_SMEM_U32 (REL_W + 128 + 8)
#define EDGE_SMEM_BYTES (EDGE_SMEM_U32 * 4)
#define ESTR 132

__device__ __forceinline__ void ldA(uint32_t ah[2][4], uint32_t al[2][4],
                                    uint32_t aAddrH, uint32_t aAddrL, uint32_t kb) {
#pragma unroll
    for (int mt = 0; mt < 2; mt++) {
        ldsm_x4(ah[mt][0], ah[mt][1], ah[mt][2], ah[mt][3],
                aAddrH + mt * (16 * WSTR * 4) + kb);
        ldsm_x4(al[mt][0], al[mt][1], al[mt][2], al[mt][3],
                aAddrL + mt * (16 * WSTR * 4) + kb);
    }
}
__device__ __forceinline__ void ldB(uint32_t bh[4][2], uint32_t bAddr, int h,
                                    uint32_t kb) {
#pragma unroll
    for (int p = 0; p < 2; p++)
        ldsm_x4(bh[2 * p][0], bh[2 * p][1], bh[2 * p + 1][0], bh[2 * p + 1][1],
                bAddr + (h * 2 + p) * (16 * WSTR * 4) + kb);
}
__device__ __forceinline__ void mmas(float acc[2][8][4], int h,
                                     uint32_t ah[2][4], uint32_t al[2][4],
                                     uint32_t bh[4][2]) {
#pragma unroll
    for (int mt = 0; mt < 2; mt++)
#pragma unroll
        for (int nt = 0; nt < 4; nt++) {
            float* a = acc[mt][h * 4 + nt];
            mma16816(a, al[mt][0], al[mt][1], al[mt][2], al[mt][3],
                     bh[nt][0], bh[nt][1]);
            mma16816(a, ah[mt][0], ah[mt][1], ah[mt][2], ah[mt][3],
                     bh[nt][0], bh[nt][1]);
        }
}

__device__ __forceinline__ void gemm_pass(
    float acc[2][8][4],
    uint32_t aAddrH, uint32_t aAddrL, uint32_t bAddr) {
    uint32_t ah[2][4], al[2][4], bh0[4][2], bh1[4][2];
    ldA(ah, al, aAddrH, aAddrL, 0);
    ldB(bh0, bAddr, 0, 0);
#pragma unroll
    for (int kk = 0; kk < 8; kk++) {
        const uint32_t kb = kk * 32;
        ldB(bh1, bAddr, 1, kb);          // B half1 latency hides under half0 MMAs
        mmas(acc, 0, ah, al, bh0);
        uint32_t ahn[2][4], aln[2][4], bh0n[4][2];
        if (kk < 7) {                    // next-kk A/B0 hide under half1 MMAs
            ldA(ahn, aln, aAddrH, aAddrL, kb + 32);
            ldB(bh0n, bAddr, 0, kb + 32);
        }
        mmas(acc, 1, ah, al, bh1);
        if (kk < 7) {
#pragma unroll
            for (int mt = 0; mt < 2; mt++)
#pragma unroll
                for (int e = 0; e < 4; e++) {
                    ah[mt][e] = ahn[mt][e];
                    al[mt][e] = aln[mt][e];
                }
#pragma unroll
            for (int nt = 0; nt < 4; nt++) {
                bh0[nt][0] = bh0n[nt][0];
                bh0[nt][1] = bh0n[nt][1];
            }
        }
    }
}

__global__ __launch_bounds__(256, 2) void edge_kernel(
    const int* __restrict__ seq_idx,
    const float* __restrict__ b_e1, const float* __restrict__ b_e2,
    const float* __restrict__ g_e, const float* __restrict__ be_e,
    float* __restrict__ out_edge) {
    extern __shared__ uint32_t smw[];
    uint32_t* Xh = smw + XH_W;
    uint32_t* Xl = smw + XL_W;
    uint32_t* Ws = smw + WS_W;
    int* s_rel = (int*)(smw + REL_W);
    float* E = (float*)smw;

    const int tid = threadIdx.x, w = tid >> 5, l = tid & 31;
    const int g = l >> 2, tig = l & 3;
    const int wm = w >> 1, wn = w & 1;     // 4 x 2 warp grid, 32x64 tiles
    const int m0 = wm * 32, n0 = wn * 64;
    const int bid = blockIdx.x;
    const int jt = bid % 3, i = (bid / 3) % NN, b = bid / (3 * NN);
    const int j0 = jt * 128;

    const uint32_t sb = smem_u32(smw);
    const int l16 = l & 15, lhi = l >> 4;
    const uint32_t aAddrH = sb + ((m0 + l16) * WSTR + lhi * 4) * 4;
    const uint32_t aAddrL = aAddrH + XL_W * 4;
    const int nB = n0 + (l & 7) + (lhi << 3);
    const int kofB = ((l >> 3) & 1) << 2;
    const uint32_t bAddr = sb + (WS_W + nB * WSTR + kofB) * 4;

    if (tid < 128) {
        int rel = seq_idx[b * NN + i] - seq_idx[b * NN + j0 + tid] + 1000;
        s_rel[tid] = min(max(rel, 0), 2047);
    }
    {
        const float4* Wsrc = (const float4*)g_W1f;
        for (int m = tid; m < 2048; m += 256) {
            int n = m >> 4, c4 = m & 15;
            *(float4*)&Ws[n * WSTR + c4 * 4] = Wsrc[m];
        }
    }
    __syncthreads();

    // Build X = relu(table[rel_j] + L_i + R_j), fp16 hi/lo, warp-per-row.
    {
        const float4 Lv = ((const float4*)(g_eL + (size_t)(b * NN + i) * CZv))[l];
        unsigned long long* Xh64 = (unsigned long long*)Xh;
        unsigned long long* Xl64 = (unsigned long long*)Xl;
#pragma unroll 4
        for (int it = 0; it < 16; it++) {
            const int r = w * 16 + it;
            float4 tv = ((const float4*)(g_table + (size_t)s_rel[r] * CZv))[l];
            float4 rv = ((const float4*)(g_eR + (size_t)(b * NN + j0 + r) * CZv))[l];
            float x0 = fmaxf(tv.x + Lv.x + rv.x, 0.0f);
            float x1 = fmaxf(tv.y + Lv.y + rv.y, 0.0f);
            float x2 = fmaxf(tv.z + Lv.z + rv.z, 0.0f);
            float x3 = fmaxf(tv.w + Lv.w + rv.w, 0.0f);
            float r0, r1, r2, r3;
            uint32_t h01 = packh_hi2(x0, x1, r0, r1);
            uint32_t h23 = packh_hi2(x2, x3, r2, r3);
            int idx64 = r * 34 + l;
            Xh64[idx64] = ((unsigned long long)h23 << 32) | h01;
            Xl64[idx64] = ((unsigned long long)packh2(r2, r3) << 32) | packh2(r0, r1);
        }
    }
    __syncthreads();

    // ---- GEMM1 ----
    float acc[2][8][4];
#pragma unroll
    for (int mt = 0; mt < 2; mt++)
#pragma unroll
        for (int nt = 0; nt < 8; nt++)
#pragma unroll
            for (int e = 0; e < 4; e++) acc[mt][nt][e] = 0.0f;
    gemm_pass(acc, aAddrH, aAddrL, bAddr);
    __syncthreads();

    // H = relu(acc + b_e1) -> X buffers via stmatrix; stage W2.
#pragma unroll
    for (int mt = 0; mt < 2; mt++) {
#pragma unroll
        for (int ntq = 0; ntq < 4; ntq++) {
            const int nt0 = 2 * ntq, nt1 = nt0 + 1;
            const int c0 = n0 + nt0 * 8 + 2 * tig;
            const int c1 = n0 + nt1 * 8 + 2 * tig;
            float bb0 = __ldg(b_e1 + c0), bb1 = __ldg(b_e1 + c0 + 1);
            float bb2 = __ldg(b_e1 + c1), bb3 = __ldg(b_e1 + c1 + 1);
            float q0, q1, q2, q3, q4, q5, q6, q7;
            uint32_t m0h = packh_hi2(fmaxf(acc[mt][nt0][0] + bb0, 0.0f),
                                     fmaxf(acc[mt][nt0][1] + bb1, 0.0f), q0, q1);
            uint32_t m1h = packh_hi2(fmaxf(acc[mt][nt0][2] + bb0, 0.0f),
                                     fmaxf(acc[mt][nt0][3] + bb1, 0.0f), q2, q3);
            uint32_t m2h = packh_hi2(fmaxf(acc[mt][nt1][0] + bb2, 0.0f),
                                     fmaxf(acc[mt][nt1][1] + bb3, 0.0f), q4, q5);
            uint32_t m3h = packh_hi2(fmaxf(acc[mt][nt1][2] + bb2, 0.0f),
                                     fmaxf(acc[mt][nt1][3] + bb3, 0.0f), q6, q7);
            uint32_t sa = sb + ((m0 + mt * 16 + l16) * WSTR
                                + (n0 >> 1) + ntq * 8 + lhi * 4) * 4;
            stsm_x4(sa, m0h, m1h, m2h, m3h);
            stsm_x4(sa + XL_W * 4, packh2(q0, q1), packh2(q2, q3),
                    packh2(q4, q5), packh2(q6, q7));
        }
    }
    {
        const float4* Wsrc = (const float4*)g_W2f;
        for (int m = tid; m < 2048; m += 256) {
            int n = m >> 4, c4 = m & 15;
            *(float4*)&Ws[n * WSTR + c4 * 4] = Wsrc[m];
        }
    }
    __syncthreads();

    // ---- GEMM2 ----
#pragma unroll
    for (int mt = 0; mt < 2; mt++)
#pragma unroll
        for (int nt = 0; nt < 8; nt++)
#pragma unroll
            for (int e = 0; e < 4; e++) acc[mt][nt][e] = 0.0f;
    gemm_pass(acc, aAddrH, aAddrL, bAddr);
    __syncthreads();

    // O = acc + b_e2 -> E[r][c]
#pragma unroll
    for (int mt = 0; mt < 2; mt++) {
        int r0w = m0 + mt * 16 + g;
#pragma unroll
        for (int nt = 0; nt < 8; nt++) {
            int c0 = n0 + nt * 8 + 2 * tig;
            float bb0 = __ldg(b_e2 + c0), bb1 = __ldg(b_e2 + c0 + 1);
            *(float2*)&E[r0w * ESTR + c0] =
                make_float2(acc[mt][nt][0] + bb0, acc[mt][nt][1] + bb1);
            *(float2*)&E[(r0w + 8) * ESTR + c0] =
                make_float2(acc[mt][nt][2] + bb0, acc[mt][nt][3] + bb1);
        }
    }
    __syncthreads();

    // LayerNorm + coalesced store.
    {
        const float ge0 = g_e[l], ge1 = g_e[32 + l], ge2 = g_e[64 + l], ge3 = g_e[96 + l];
        const float be0 = be_e[l], be1 = be_e[32 + l], be2 = be_e[64 + l], be3 = be_e[96 + l];
#pragma unroll 2
        for (int rr = 0; rr < 16; rr++) {
            const int r = w * 16 + rr;
            float v0 = E[r * ESTR + l];
            float v1 = E[r * ESTR + 32 + l];
            float v2 = E[r * ESTR + 64 + l];
            float v3 = E[r * ESTR + 96 + l];
            float s = v0 + v1 + v2 + v3;
#pragma unroll
            for (int off = 16; off > 0; off >>= 1) s += __shfl_xor_sync(0xffffffffu, s, off);
            float mean = s * (1.0f / 128.0f);
            float d0 = v0 - mean, d1 = v1 - mean, d2 = v2 - mean, d3 = v3 - mean;
            float sq = d0 * d0 + d1 * d1 + d2 * d2 + d3 * d3;
#pragma unroll
            for (int off = 16; off > 0; off >>= 1) sq += __shfl_xor_sync(0xffffffffu, sq, off);
            float rstd = rsqrtf(sq * (1.0f / 128.0f) + LN_EPS);
            float* dst = out_edge + ((size_t)(b * NN + i) * NN + (j0 + r)) * CZv;
            dst[l] = d0 * rstd * ge0 + be0;
            dst[32 + l] = d1 * rstd * ge1 + be1;
            dst[64 + l] = d2 * rstd * ge2 + be2;
            dst[96 + l] = d3 * rstd * ge3 + be3;
        }
    }
}

// ===========================================================================
extern "C" void kernel_launch(void* const* d_in, const int* in_sizes, int n_in,
                              void* d_out, int out_size) {
    const int* seq_idx = (const int*)d_in[0];
    const float* seq_feat = (const float*)d_in[1];
    const float* timestep = (const float*)d_in[2];
    const float* frame_mask = (const float*)d_in[3];
    const float* W_npos = (const float*)d_in[4];
    const float* b_npos = (const float*)d_in[5];
    const float* W_ntf = (const float*)d_in[6];
    const float* b_ntf = (const float*)d_in[7];
    const float* W_ntime = (const float*)d_in[8];
    const float* b_ntime = (const float*)d_in[9];
    const float* W_n1 = (const float*)d_in[10];
    const float* b_n1 = (const float*)d_in[11];
    const float* W_n2 = (const float*)d_in[12];
    const float* b_n2 = (const float*)d_in[13];
    const float* g_n = (const float*)d_in[14];
    const float* be_n = (const float*)d_in[15];
    const float* W_epos = (const float*)d_in[16];
    const float* b_epos = (const float*)d_in[17];
    const float* W_etf = (const float*)d_in[18];
    const float* b_etf = (const float*)d_in[19];
    const float* W_etime = (const float*)d_in[20];
    const float* b_etime = (const float*)d_in[21];
    const float* W_e1 = (const float*)d_in[22];
    const float* b_e1 = (const float*)d_in[23];
    const float* W_e2 = (const float*)d_in[24];
    const float* b_e2 = (const float*)d_in[25];
    const float* g_e = (const float*)d_in[26];
    const float* be_e = (const float*)d_in[27];

    float* out = (float*)d_out;
    float* out_seq = out;                   // [B,N,CS] first
    float* out_edge = out + NB * NN * CSv;  // then [B,N,N,CZ]

    static int configured = 0;
    if (!configured) {
        cudaFuncSetAttribute(edge_kernel, cudaFuncAttributeMaxDynamicSharedMemorySize,
                             EDGE_SMEM_BYTES);
        configured = 1;
    }

    setup_kernel<<<TBLK + NODEB + 64, 256>>>(
        seq_idx, seq_feat, timestep, frame_mask,
        W_npos, b_npos, W_ntf, b_ntf, W_ntime, b_ntime,
        W_n1, b_n1, W_n2, b_n2, g_n, be_n,
        W_epos, b_epos, b_etf, b_etime, W_etf, W_etime,
        W_e1, W_e2, out_seq);
    edge_kernel<<<NB * NN * 3, 256, EDGE_SMEM_BYTES>>>(seq_idx, b_e1, b_e2,
                                                       g_e, be_e, out_edge);
}

// round 12
// speedup vs baseline: 1.1491x; 1.1491x over previous
#include <cuda_runtime.h>
#include <cuda_fp16.h>
#include <cstdint>

#define NB 2
#define NN 384
#define TFv 22
#define POSv 32
#define TPROJv 33
#define CSv 256
#define CZv 128
#define LN_EPS 1e-5f
#define PI_F 3.14159265358979323846f

__device__ float g_table[2048 * CZv];
__device__ float g_eL[NB * NN * CZv];
__device__ float g_eR[NB * NN * CZv];
__device__ __half g_W1f[CZv * CZv], g_W2f[CZv * CZv];

// ---------------------------------------------------------------------------
// helpers
// ---------------------------------------------------------------------------
__device__ __forceinline__ uint32_t smem_u32(const void* p) {
    uint32_t a;
    asm("{ .reg .u64 t; cvta.to.shared.u64 t, %1; cvt.u32.u64 %0, t; }"
        : "=r"(a) : "l"(p));
    return a;
}
__device__ __forceinline__ uint32_t packh_hi2(float x0, float x1, float& r0, float& r1) {
    __half2 v = __floats2half2_rn(x0, x1);
    r0 = x0 - __half2float(__low2half(v));
    r1 = x1 - __half2float(__high2half(v));
    return *reinterpret_cast<uint32_t*>(&v);
}
__device__ __forceinline__ uint32_t packh2(float r0, float r1) {
    __half2 v = __floats2half2_rn(r0, r1);
    return *reinterpret_cast<uint32_t*>(&v);
}
__device__ __forceinline__ void mma16816(float* c, uint32_t a0, uint32_t a1,
                                         uint32_t a2, uint32_t a3,
                                         uint32_t b0, uint32_t b1) {
    asm volatile(
        "mma.sync.aligned.m16n8k16.row.col.f32.f16.f16.f32 "
        "{%0,%1,%2,%3}, {%4,%5,%6,%7}, {%8,%9}, {%0,%1,%2,%3};"
        : "+f"(c[0]), "+f"(c[1]), "+f"(c[2]), "+f"(c[3])
        : "r"(a0), "r"(a1), "r"(a2), "r"(a3), "r"(b0), "r"(b1));
}
__device__ __forceinline__ void ldsm_x4(uint32_t& r0, uint32_t& r1,
                                        uint32_t& r2, uint32_t& r3, uint32_t addr) {
    asm volatile("ldmatrix.sync.aligned.m8n8.x4.shared.b16 {%0,%1,%2,%3}, [%4];"
                 : "=r"(r0), "=r"(r1), "=r"(r2), "=r"(r3) : "r"(addr));
}

// ---------------------------------------------------------------------------
// Fused setup kernel (unchanged — correctness proven).
// ---------------------------------------------------------------------------
#define NR 8
#define TBLK 1024
#define NODEB (NB * NN / NR)   // 96

__global__ __launch_bounds__(256) void setup_kernel(
    const int* __restrict__ seq_idx, const float* __restrict__ seq_feat,
    const float* __restrict__ timestep, const float* __restrict__ frame_mask,
    const float* __restrict__ W_npos, const float* __restrict__ b_npos,
    const float* __restrict__ W_ntf, const float* __restrict__ b_ntf,
    const float* __restrict__ W_ntime, const float* __restrict__ b_ntime,
    const float* __restrict__ W_n1, const float* __restrict__ b_n1,
    const float* __restrict__ W_n2, const float* __restrict__ b_n2,
    const float* __restrict__ g_n, const float* __restrict__ be_n,
    const float* __restrict__ W_epos, const float* __restrict__ b_epos,
    const float* __restrict__ b_etf, const float* __restrict__ b_etime,
    const float* __restrict__ W_etf, const float* __restrict__ W_etime,
    const float* __restrict__ W_e1, const float* __restrict__ W_e2,
    float* __restrict__ out_seq) {
    __shared__ float su[4352];
    const int tid = threadIdx.x;
    const int bid = blockIdx.x;

    if (bid < TBLK) {
        float* sWe = su;
        float* emb = su + 4224;
        const int half = tid >> 7, c = tid & 127;
        for (int m = tid; m < CZv * POSv; m += 256)
            sWe[(m >> 5) * 33 + (m & 31)] = W_epos[m];
        const int relv = bid * 2 + half - 1000;
        if (c < 16) {
            float p = powf(2056.0f, (float)c * (1.0f / 16.0f));
            float ang = ((float)relv * PI_F) / p;
            emb[half * 32 + c] = sinf(ang);
            emb[half * 32 + c + 16] = cosf(ang);
        }
        __syncthreads();
        float acc = b_epos[c] + b_etf[c] + b_etime[c];
#pragma unroll
        for (int k = 0; k < POSv; k++) acc += emb[half * 32 + k] * sWe[c * 33 + k];
        g_table[(bid * 2 + half) * CZv + c] = acc;
        return;
    }
    if (bid >= TBLK + NODEB) {
        int t = (bid - TBLK - NODEB) * 256 + tid;
        g_W1f[t] = __float2half_rn(W_e1[t]);
        g_W2f[t] = __float2half_rn(W_e2[t]);
        return;
    }

    float (*spemb)[POSv] = (float(*)[POSv])su;
    float (*stemb)[36] = (float(*)[36])(su + 256);
    float (*sfeat)[24] = (float(*)[24])(su + 544);
    float (*sx)[CSv] = (float(*)[CSv])(su + 736);
    const int row0 = (bid - TBLK) * NR;

    {
        const int r = tid >> 5, j = tid & 31;
        const int row = row0 + r;
        const int b = row / NN;
        if (j < TFv) sfeat[r][j] = seq_feat[row * TFv + j];
        if (j < 16) {
            float p = powf(2056.0f, (float)j * (1.0f / 16.0f));
            float ang = ((float)seq_idx[row] * PI_F) / p;
            spemb[r][j] = sinf(ang);
            spemb[r][j + 16] = cosf(ang);
            float fm = frame_mask[row];
            float tt = timestep[b] * fm;
            float fr = expf(-0.6140226914650789f * (float)j);
            float a2 = tt * fr;
            stemb[r][j] = sinf(a2);
            stemb[r][j + 16] = cosf(a2);
            if (j == 0) stemb[r][32] = fm;
        }
    }
    __syncthreads();

    const int c = tid;
    float acc[NR];
    {
        float base = b_npos[c] + b_ntf[c] + b_ntime[c];
#pragma unroll
        for (int r = 0; r < NR; r++) acc[r] = base;
    }
#pragma unroll
    for (int k = 0; k < POSv; k++) {
        float wv = W_npos[c * POSv + k];
#pragma unroll
        for (int r = 0; r < NR; r++) acc[r] += spemb[r][k] * wv;
    }
#pragma unroll
    for (int k = 0; k < TFv; k++) {
        float wv = W_ntf[c * TFv + k];
#pragma unroll
        for (int r = 0; r < NR; r++) acc[r] += sfeat[r][k] * wv;
    }
#pragma unroll
    for (int k = 0; k < TPROJv; k++) {
        float wv = W_ntime[c * TPROJv + k];
#pragma unroll
        for (int r = 0; r < NR; r++) acc[r] += stemb[r][k] * wv;
    }
#pragma unroll
    for (int r = 0; r < NR; r++) sx[r][c] = fmaxf(acc[r], 0.0f);

    {
        const int c2 = tid & 127, half = tid >> 7;
        float e[NR];
#pragma unroll
        for (int r = 0; r < NR; r++) e[r] = 0.0f;
#pragma unroll
        for (int k = 0; k < TFv; k++) {
            float wv = W_etf[c2 * (2 * TFv) + half * TFv + k];
#pragma unroll
            for (int r = 0; r < NR; r++) e[r] += sfeat[r][k] * wv;
        }
#pragma unroll
        for (int k = 0; k < TPROJv; k++) {
            float wv = W_etime[c2 * (2 * TPROJv) + half * TPROJv + k];
#pragma unroll
            for (int r = 0; r < NR; r++) e[r] += stemb[r][k] * wv;
        }
        float* dst = half ? g_eR : g_eL;
#pragma unroll
        for (int r = 0; r < NR; r++) dst[(row0 + r) * CZv + c2] = e[r];
    }
    __syncthreads();

    float h[NR];
#pragma unroll
    for (int r = 0; r < NR; r++) h[r] = b_n1[c];
    {
        const float4* W1r = (const float4*)(W_n1 + c * CSv);
#pragma unroll 4
        for (int q = 0; q < CSv / 4; q++) {
            float4 wv = W1r[q];
#pragma unroll
            for (int r = 0; r < NR; r++) {
                float4 xv = *(const float4*)&sx[r][q * 4];
                h[r] += xv.x * wv.x + xv.y * wv.y + xv.z * wv.z + xv.w * wv.w;
            }
        }
    }
    __syncthreads();
#pragma unroll
    for (int r = 0; r < NR; r++) sx[r][c] = fmaxf(h[r], 0.0f);
    __syncthreads();

    float o[NR];
#pragma unroll
    for (int r = 0; r < NR; r++) o[r] = b_n2[c];
    {
        const float4* W2r = (const float4*)(W_n2 + c * CSv);
#pragma unroll 4
        for (int q = 0; q < CSv / 4; q++) {
            float4 wv = W2r[q];
#pragma unroll
            for (int r = 0; r < NR; r++) {
                float4 xv = *(const float4*)&sx[r][q * 4];
                o[r] += xv.x * wv.x + xv.y * wv.y + xv.z * wv.z + xv.w * wv.w;
            }
        }
    }
    __syncthreads();
#pragma unroll
    for (int r = 0; r < NR; r++) sx[r][c] = o[r];
    __syncthreads();

    {
        const int w = tid >> 5, l = tid & 31;
        float v[8];
#pragma unroll
        for (int g = 0; g < 8; g++) v[g] = sx[w][g * 32 + l];
        float s = 0.0f;
#pragma unroll
        for (int g = 0; g < 8; g++) s += v[g];
#pragma unroll
        for (int off = 16; off > 0; off >>= 1) s += __shfl_xor_sync(0xffffffffu, s, off);
        float mean = s * (1.0f / 256.0f);
        float sq = 0.0f;
#pragma unroll
        for (int g = 0; g < 8; g++) { float d = v[g] - mean; sq += d * d; }
#pragma unroll
        for (int off = 16; off > 0; off >>= 1) sq += __shfl_xor_sync(0xffffffffu, sq, off);
        float rstd = rsqrtf(sq * (1.0f / 256.0f) + LN_EPS);
        const int row = row0 + w;
#pragma unroll
        for (int g = 0; g < 8; g++) {
            int cc = g * 32 + l;
            out_seq[row * CSv + cc] = (v[g] - mean) * rstd * g_n[cc] + be_n[cc];
        }
    }
}

// ---------------------------------------------------------------------------
// Edge kernel v2: warp-autonomous. 8 warps x (16 rows x 128 cols).
// H lives in registers (C-frag == A-frag identity). Only 2 block syncs.
// ---------------------------------------------------------------------------
#define WSTR 68
#define XH_W 0
#define XL_W (128 * WSTR)
#define WS_W (2 * 128 * WSTR)
#define REL_W (3 * 128 * WSTR)
#define EDGE_SMEM_U32 (REL_W + 128 + 8)
#define EDGE_SMEM_BYTES (EDGE_SMEM_U32 * 4)

__global__ __launch_bounds__(256, 2) void edge_kernel(
    const int* __restrict__ seq_idx,
    const float* __restrict__ b_e1, const float* __restrict__ b_e2,
    const float* __restrict__ g_e, const float* __restrict__ be_e,
    float* __restrict__ out_edge) {
    extern __shared__ uint32_t smw[];
    uint32_t* Xh = smw + XH_W;
    uint32_t* Xl = smw + XL_W;
    uint32_t* Ws = smw + WS_W;
    int* s_rel = (int*)(smw + REL_W);

    const int tid = threadIdx.x, w = tid >> 5, l = tid & 31;
    const int g = l >> 2, tig = l & 3;
    const int m0 = w * 16;                 // warp's 16 rows
    const int bid = blockIdx.x;
    const int jt = bid % 3, i = (bid / 3) % NN, b = bid / (3 * NN);
    const int j0 = jt * 128;

    const uint32_t sb = smem_u32(smw);
    const int l16 = l & 15, lhi = l >> 4;
    const uint32_t aAddrH = sb + ((m0 + l16) * WSTR + lhi * 4) * 4;
    const uint32_t aAddrL = aAddrH + XL_W * 4;
    const int nB = (l & 7) + (lhi << 3);   // 0..15
    const int kofB = ((l >> 3) & 1) << 2;
    const uint32_t bAddr1 = sb + (WS_W + nB * WSTR + kofB) * 4;   // W1 region
    const uint32_t bAddr2 = sb + (nB * WSTR + kofB) * 4;          // W2 in Xh region

    if (tid < 128) {
        int rel = seq_idx[b * NN + i] - seq_idx[b * NN + j0 + tid] + 1000;
        s_rel[tid] = min(max(rel, 0), 2047);
    }
    {   // stage W1 into Ws (cooperative)
        const float4* Wsrc = (const float4*)g_W1f;
        for (int m = tid; m < 2048; m += 256) {
            int n = m >> 4, c4 = m & 15;
            *(float4*)&Ws[n * WSTR + c4 * 4] = Wsrc[m];
        }
    }
    __syncthreads();   // sync #1: rel + W1 visible

    // ---- X build (own 16 rows), fp16 hi/lo ----
    {
        const float4 Lv = ((const float4*)(g_eL + (size_t)(b * NN + i) * CZv))[l];
        unsigned long long* Xh64 = (unsigned long long*)Xh;
        unsigned long long* Xl64 = (unsigned long long*)Xl;
#pragma unroll 4
        for (int it = 0; it < 16; it++) {
            const int r = m0 + it;
            float4 tv = ((const float4*)(g_table + (size_t)s_rel[r] * CZv))[l];
            float4 rv = ((const float4*)(g_eR + (size_t)(b * NN + j0 + r) * CZv))[l];
            float x0 = fmaxf(tv.x + Lv.x + rv.x, 0.0f);
            float x1 = fmaxf(tv.y + Lv.y + rv.y, 0.0f);
            float x2 = fmaxf(tv.z + Lv.z + rv.z, 0.0f);
            float x3 = fmaxf(tv.w + Lv.w + rv.w, 0.0f);
            float r0, r1, r2, r3;
            uint32_t h01 = packh_hi2(x0, x1, r0, r1);
            uint32_t h23 = packh_hi2(x2, x3, r2, r3);
            int idx64 = r * 34 + l;
            Xh64[idx64] = ((unsigned long long)h23 << 32) | h01;
            Xl64[idx64] = ((unsigned long long)packh2(r2, r3) << 32) | packh2(r0, r1);
        }
    }
    __syncwarp();      // own rows only: warp-local visibility

    // ---- GEMM1: acc1[16 nt][4] = X(16xk128) @ W1^T ----
    float acc1[16][4];
#pragma unroll
    for (int nt = 0; nt < 16; nt++)
#pragma unroll
        for (int e = 0; e < 4; e++) acc1[nt][e] = 0.0f;
#pragma unroll
    for (int kk = 0; kk < 8; kk++) {
        const uint32_t kb = kk * 32;
        uint32_t ah[4], al[4];
        ldsm_x4(ah[0], ah[1], ah[2], ah[3], aAddrH + kb);
        ldsm_x4(al[0], al[1], al[2], al[3], aAddrL + kb);
#pragma unroll
        for (int p = 0; p < 8; p++) {
            uint32_t bf[4];
            ldsm_x4(bf[0], bf[1], bf[2], bf[3], bAddr1 + p * (16 * WSTR * 4) + kb);
            mma16816(acc1[2 * p], al[0], al[1], al[2], al[3], bf[0], bf[1]);
            mma16816(acc1[2 * p], ah[0], ah[1], ah[2], ah[3], bf[0], bf[1]);
            mma16816(acc1[2 * p + 1], al[0], al[1], al[2], al[3], bf[2], bf[3]);
            mma16816(acc1[2 * p + 1], ah[0], ah[1], ah[2], ah[3], bf[2], bf[3]);
        }
    }

    // ---- Transform: H = relu(acc1 + b_e1) -> A-fragments (identity map) ----
    uint32_t Ah[8][4], Al[8][4];
#pragma unroll
    for (int q = 0; q < 8; q++) {
        const int c0 = 16 * q + 2 * tig;       // nt = 2q
        const int c1 = 16 * q + 8 + 2 * tig;   // nt = 2q+1
        float b00 = __ldg(b_e1 + c0), b01 = __ldg(b_e1 + c0 + 1);
        float b10 = __ldg(b_e1 + c1), b11 = __ldg(b_e1 + c1 + 1);
        float r0, r1, r2, r3, r4, r5, r6, r7;
        Ah[q][0] = packh_hi2(fmaxf(acc1[2 * q][0] + b00, 0.0f),
                             fmaxf(acc1[2 * q][1] + b01, 0.0f), r0, r1);
        Ah[q][1] = packh_hi2(fmaxf(acc1[2 * q][2] + b00, 0.0f),
                             fmaxf(acc1[2 * q][3] + b01, 0.0f), r2, r3);
        Ah[q][2] = packh_hi2(fmaxf(acc1[2 * q + 1][0] + b10, 0.0f),
                             fmaxf(acc1[2 * q + 1][1] + b11, 0.0f), r4, r5);
        Ah[q][3] = packh_hi2(fmaxf(acc1[2 * q + 1][2] + b10, 0.0f),
                             fmaxf(acc1[2 * q + 1][3] + b11, 0.0f), r6, r7);
        Al[q][0] = packh2(r0, r1);
        Al[q][1] = packh2(r2, r3);
        Al[q][2] = packh2(r4, r5);
        Al[q][3] = packh2(r6, r7);
    }

    // ---- Stage W2 rows m0..m0+15 into OWN Xh slice (X dead for this warp) ----
    {
        const float4* Wsrc = (const float4*)g_W2f;
#pragma unroll
        for (int it = 0; it < 8; it++) {
            int idx = it * 32 + l;
            int rn = m0 + (idx >> 4), c4 = idx & 15;
            *(float4*)&Xh[rn * WSTR + c4 * 4] = Wsrc[rn * 16 + c4];
        }
    }
    __syncthreads();   // sync #2: all W2 slices staged

    // ---- GEMM2 in two 64-col halves (A = Ah/Al registers, B = W2 in Xh) ----
    float sumA = 0.0f, sqA = 0.0f, sumB = 0.0f, sqB = 0.0f;
    float* E0 = (float*)(Xl + m0 * WSTR);   // own Xl slice: park half0
    const float* ge = g_e;
    const float* bee = be_e;

    float acc2[8][4];
#pragma unroll
    for (int h = 0; h < 2; h++) {
#pragma unroll
        for (int nt = 0; nt < 8; nt++)
#pragma unroll
            for (int e = 0; e < 4; e++) acc2[nt][e] = 0.0f;
#pragma unroll
        for (int kk = 0; kk < 8; kk++) {
            const uint32_t kb = kk * 32;
#pragma unroll
            for (int p = 0; p < 4; p++) {
                uint32_t bf[4];
                ldsm_x4(bf[0], bf[1], bf[2], bf[3],
                        bAddr2 + (h * 4 + p) * (16 * WSTR * 4) + kb);
                mma16816(acc2[2 * p], Al[kk][0], Al[kk][1], Al[kk][2], Al[kk][3],
                         bf[0], bf[1]);
                mma16816(acc2[2 * p], Ah[kk][0], Ah[kk][1], Ah[kk][2], Ah[kk][3],
                         bf[0], bf[1]);
                mma16816(acc2[2 * p + 1], Al[kk][0], Al[kk][1], Al[kk][2], Al[kk][3],
                         bf[2], bf[3]);
                mma16816(acc2[2 * p + 1], Ah[kk][0], Ah[kk][1], Ah[kk][2], Ah[kk][3],
                         bf[2], bf[3]);
            }
        }
        // bias + stats; half0 -> park in E0; half1 stays in acc2 (store below)
#pragma unroll
        for (int nt = 0; nt < 8; nt++) {
            const int col = h * 64 + 8 * nt + 2 * tig;
            float bb0 = __ldg(b_e2 + col), bb1 = __ldg(b_e2 + col + 1);
            float v0 = acc2[nt][0] + bb0, v1 = acc2[nt][1] + bb1;
            float v2 = acc2[nt][2] + bb0, v3 = acc2[nt][3] + bb1;
            sumA += v0 + v1; sqA += v0 * v0 + v1 * v1;
            sumB += v2 + v3; sqB += v2 * v2 + v3 * v3;
            if (h == 0) {
                *(float2*)&E0[g * WSTR + 8 * nt + 2 * tig] = make_float2(v0, v1);
                *(float2*)&E0[(g + 8) * WSTR + 8 * nt + 2 * tig] = make_float2(v2, v3);
            } else {
                acc2[nt][0] = v0; acc2[nt][1] = v1;
                acc2[nt][2] = v2; acc2[nt][3] = v3;
            }
        }
    }

    // ---- LN stats: reduce over the 4-lane quad (rows g and g+8) ----
#pragma unroll
    for (int off = 1; off <= 2; off <<= 1) {
        sumA += __shfl_xor_sync(0xffffffffu, sumA, off);
        sqA += __shfl_xor_sync(0xffffffffu, sqA, off);
        sumB += __shfl_xor_sync(0xffffffffu, sumB, off);
        sqB += __shfl_xor_sync(0xffffffffu, sqB, off);
    }
    const float mA = sumA * (1.0f / 128.0f);
    const float rA = rsqrtf(fmaxf(sqA * (1.0f / 128.0f) - mA * mA, 0.0f) + LN_EPS);
    const float mB = sumB * (1.0f / 128.0f);
    const float rB = rsqrtf(fmaxf(sqB * (1.0f / 128.0f) - mB * mB, 0.0f) + LN_EPS);

    const size_t rowbase = ((size_t)(b * NN + i) * NN + (j0 + m0));

    // half1 (cols 64..127) directly from registers: lane's own rows g, g+8
    {
        float* dstg = out_edge + (rowbase + g) * CZv;
        float* dstg8 = out_edge + (rowbase + g + 8) * CZv;
#pragma unroll
        for (int nt = 0; nt < 8; nt++) {
            const int col = 64 + 8 * nt + 2 * tig;
            float ge0 = __ldg(ge + col), ge1 = __ldg(ge + col + 1);
            float be0 = __ldg(bee + col), be1 = __ldg(bee + col + 1);
            *(float2*)&dstg[col] = make_float2(
                (acc2[nt][0] - mA) * rA * ge0 + be0,
                (acc2[nt][1] - mA) * rA * ge1 + be1);
            *(float2*)&dstg8[col] = make_float2(
                (acc2[nt][2] - mB) * rB * ge0 + be0,
                (acc2[nt][3] - mB) * rB * ge1 + be1);
        }
    }
    __syncwarp();   // E0 writes (all lanes) visible before cross-lane reads

    // half0 (cols 0..63) coalesced from E0 with shuffled stats
    {
        const float ge0 = ge[l], ge1 = ge[32 + l];
        const float be0 = bee[l], be1 = bee[32 + l];
#pragma unroll 2
        for (int r = 0; r < 16; r++) {
            const int src = 4 * (r & 7);
            float m1 = __shfl_sync(0xffffffffu, mA, src);
            float m2 = __shfl_sync(0xffffffffu, mB, src);
            float r1 = __shfl_sync(0xffffffffu, rA, src);
            float r2 = __shfl_sync(0xffffffffu, rB, src);
            float mean = (r < 8) ? m1 : m2;
            float rstd = (r < 8) ? r1 : r2;
            float v0 = E0[r * WSTR + l];
            float v1 = E0[r * WSTR + 32 + l];
            float* dst = out_edge + (rowbase + r) * CZv;
            dst[l] = (v0 - mean) * rstd * ge0 + be0;
            dst[32 + l] = (v1 - mean) * rstd * ge1 + be1;
        }
    }
}

// ===========================================================================
extern "C" void kernel_launch(void* const* d_in, const int* in_sizes, int n_in,
                              void* d_out, int out_size) {
    const int* seq_idx = (const int*)d_in[0];
    const float* seq_feat = (const float*)d_in[1];
    const float* timestep = (const float*)d_in[2];
    const float* frame_mask = (const float*)d_in[3];
    const float* W_npos = (const float*)d_in[4];
    const float* b_npos = (const float*)d_in[5];
    const float* W_ntf = (const float*)d_in[6];
    const float* b_ntf = (const float*)d_in[7];
    const float* W_ntime = (const float*)d_in[8];
    const float* b_ntime = (const float*)d_in[9];
    const float* W_n1 = (const float*)d_in[10];
    const float* b_n1 = (const float*)d_in[11];
    const float* W_n2 = (const float*)d_in[12];
    const float* b_n2 = (const float*)d_in[13];
    const float* g_n = (const float*)d_in[14];
    const float* be_n = (const float*)d_in[15];
    const float* W_epos = (const float*)d_in[16];
    const float* b_epos = (const float*)d_in[17];
    const float* W_etf = (const float*)d_in[18];
    const float* b_etf = (const float*)d_in[19];
    const float* W_etime = (const float*)d_in[20];
    const float* b_etime = (const float*)d_in[21];
    const float* W_e1 = (const float*)d_in[22];
    const float* b_e1 = (const float*)d_in[23];
    const float* W_e2 = (const float*)d_in[24];
    const float* b_e2 = (const float*)d_in[25];
    const float* g_e = (const float*)d_in[26];
    const float* be_e = (const float*)d_in[27];

    float* out = (float*)d_out;
    float* out_seq = out;
    float* out_edge = out + NB * NN * CSv;

    static int configured = 0;
    if (!configured) {
        cudaFuncSetAttribute(edge_kernel, cudaFuncAttributeMaxDynamicSharedMemorySize,
                             EDGE_SMEM_BYTES);
        configured = 1;
    }

    setup_kernel<<<TBLK + NODEB + 64, 256>>>(
        seq_idx, seq_feat, timestep, frame_mask,
        W_npos, b_npos, W_ntf, b_ntf, W_ntime, b_ntime,
        W_n1, b_n1, W_n2, b_n2, g_n, be_n,
        W_epos, b_epos, b_etf, b_etime, W_etf, W_etime,
        W_e1, W_e2, out_seq);
    edge_kernel<<<NB * NN * 3, 256, EDGE_SMEM_BYTES>>>(seq_idx, b_e1, b_e2,
                                                       g_e, be_e, out_edge);
}

// round 13
// speedup vs baseline: 1.2737x; 1.1084x over previous
#include <cuda_runtime.h>
#include <cuda_fp16.h>
#include <cstdint>

#define NB 2
#define NN 384
#define TFv 22
#define POSv 32
#define TPROJv 33
#define CSv 256
#define CZv 128
#define LN_EPS 1e-5f
#define PI_F 3.14159265358979323846f

__device__ float g_table[2048 * CZv];
__device__ float g_eL[NB * NN * CZv];
__device__ float g_eR[NB * NN * CZv];
__device__ __half g_W1f[CZv * CZv], g_W2f[CZv * CZv];

// ---------------------------------------------------------------------------
// helpers
// ---------------------------------------------------------------------------
__device__ __forceinline__ uint32_t smem_u32(const void* p) {
    uint32_t a;
    asm("{ .reg .u64 t; cvta.to.shared.u64 t, %1; cvt.u32.u64 %0, t; }"
        : "=r"(a) : "l"(p));
    return a;
}
__device__ __forceinline__ uint32_t packh_hi2(float x0, float x1, float& r0, float& r1) {
    __half2 v = __floats2half2_rn(x0, x1);
    r0 = x0 - __half2float(__low2half(v));
    r1 = x1 - __half2float(__high2half(v));
    return *reinterpret_cast<uint32_t*>(&v);
}
__device__ __forceinline__ uint32_t packh2(float r0, float r1) {
    __half2 v = __floats2half2_rn(r0, r1);
    return *reinterpret_cast<uint32_t*>(&v);
}
__device__ __forceinline__ void mma16816(float* c, uint32_t a0, uint32_t a1,
                                         uint32_t a2, uint32_t a3,
                                         uint32_t b0, uint32_t b1) {
    asm volatile(
        "mma.sync.aligned.m16n8k16.row.col.f32.f16.f16.f32 "
        "{%0,%1,%2,%3}, {%4,%5,%6,%7}, {%8,%9}, {%0,%1,%2,%3};"
        : "+f"(c[0]), "+f"(c[1]), "+f"(c[2]), "+f"(c[3])
        : "r"(a0), "r"(a1), "r"(a2), "r"(a3), "r"(b0), "r"(b1));
}
__device__ __forceinline__ void ldsm_x4(uint32_t& r0, uint32_t& r1,
                                        uint32_t& r2, uint32_t& r3, uint32_t addr) {
    asm volatile("ldmatrix.sync.aligned.m8n8.x4.shared.b16 {%0,%1,%2,%3}, [%4];"
                 : "=r"(r0), "=r"(r1), "=r"(r2), "=r"(r3) : "r"(addr));
}

// ---------------------------------------------------------------------------
// Fused setup kernel (unchanged — correctness proven).
// ---------------------------------------------------------------------------
#define NR 8
#define TBLK 1024
#define NODEB (NB * NN / NR)   // 96

__global__ __launch_bounds__(256) void setup_kernel(
    const int* __restrict__ seq_idx, const float* __restrict__ seq_feat,
    const float* __restrict__ timestep, const float* __restrict__ frame_mask,
    const float* __restrict__ W_npos, const float* __restrict__ b_npos,
    const float* __restrict__ W_ntf, const float* __restrict__ b_ntf,
    const float* __restrict__ W_ntime, const float* __restrict__ b_ntime,
    const float* __restrict__ W_n1, const float* __restrict__ b_n1,
    const float* __restrict__ W_n2, const float* __restrict__ b_n2,
    const float* __restrict__ g_n, const float* __restrict__ be_n,
    const float* __restrict__ W_epos, const float* __restrict__ b_epos,
    const float* __restrict__ b_etf, const float* __restrict__ b_etime,
    const float* __restrict__ W_etf, const float* __restrict__ W_etime,
    const float* __restrict__ W_e1, const float* __restrict__ W_e2,
    float* __restrict__ out_seq) {
    __shared__ float su[4352];
    const int tid = threadIdx.x;
    const int bid = blockIdx.x;

    if (bid < TBLK) {
        float* sWe = su;
        float* emb = su + 4224;
        const int half = tid >> 7, c = tid & 127;
        for (int m = tid; m < CZv * POSv; m += 256)
            sWe[(m >> 5) * 33 + (m & 31)] = W_epos[m];
        const int relv = bid * 2 + half - 1000;
        if (c < 16) {
            float p = powf(2056.0f, (float)c * (1.0f / 16.0f));
            float ang = ((float)relv * PI_F) / p;
            emb[half * 32 + c] = sinf(ang);
            emb[half * 32 + c + 16] = cosf(ang);
        }
        __syncthreads();
        float acc = b_epos[c] + b_etf[c] + b_etime[c];
#pragma unroll
        for (int k = 0; k < POSv; k++) acc += emb[half * 32 + k] * sWe[c * 33 + k];
        g_table[(bid * 2 + half) * CZv + c] = acc;
        return;
    }
    if (bid >= TBLK + NODEB) {
        int t = (bid - TBLK - NODEB) * 256 + tid;
        g_W1f[t] = __float2half_rn(W_e1[t]);
        g_W2f[t] = __float2half_rn(W_e2[t]);
        return;
    }

    float (*spemb)[POSv] = (float(*)[POSv])su;
    float (*stemb)[36] = (float(*)[36])(su + 256);
    float (*sfeat)[24] = (float(*)[24])(su + 544);
    float (*sx)[CSv] = (float(*)[CSv])(su + 736);
    const int row0 = (bid - TBLK) * NR;

    {
        const int r = tid >> 5, j = tid & 31;
        const int row = row0 + r;
        const int b = row / NN;
        if (j < TFv) sfeat[r][j] = seq_feat[row * TFv + j];
        if (j < 16) {
            float p = powf(2056.0f, (float)j * (1.0f / 16.0f));
            float ang = ((float)seq_idx[row] * PI_F) / p;
            spemb[r][j] = sinf(ang);
            spemb[r][j + 16] = cosf(ang);
            float fm = frame_mask[row];
            float tt = timestep[b] * fm;
            float fr = expf(-0.6140226914650789f * (float)j);
            float a2 = tt * fr;
            stemb[r][j] = sinf(a2);
            stemb[r][j + 16] = cosf(a2);
            if (j == 0) stemb[r][32] = fm;
        }
    }
    __syncthreads();

    const int c = tid;
    float acc[NR];
    {
        float base = b_npos[c] + b_ntf[c] + b_ntime[c];
#pragma unroll
        for (int r = 0; r < NR; r++) acc[r] = base;
    }
#pragma unroll
    for (int k = 0; k < POSv; k++) {
        float wv = W_npos[c * POSv + k];
#pragma unroll
        for (int r = 0; r < NR; r++) acc[r] += spemb[r][k] * wv;
    }
#pragma unroll
    for (int k = 0; k < TFv; k++) {
        float wv = W_ntf[c * TFv + k];
#pragma unroll
        for (int r = 0; r < NR; r++) acc[r] += sfeat[r][k] * wv;
    }
#pragma unroll
    for (int k = 0; k < TPROJv; k++) {
        float wv = W_ntime[c * TPROJv + k];
#pragma unroll
        for (int r = 0; r < NR; r++) acc[r] += stemb[r][k] * wv;
    }
#pragma unroll
    for (int r = 0; r < NR; r++) sx[r][c] = fmaxf(acc[r], 0.0f);

    {
        const int c2 = tid & 127, half = tid >> 7;
        float e[NR];
#pragma unroll
        for (int r = 0; r < NR; r++) e[r] = 0.0f;
#pragma unroll
        for (int k = 0; k < TFv; k++) {
            float wv = W_etf[c2 * (2 * TFv) + half * TFv + k];
#pragma unroll
            for (int r = 0; r < NR; r++) e[r] += sfeat[r][k] * wv;
        }
#pragma unroll
        for (int k = 0; k < TPROJv; k++) {
            float wv = W_etime[c2 * (2 * TPROJv) + half * TPROJv + k];
#pragma unroll
            for (int r = 0; r < NR; r++) e[r] += stemb[r][k] * wv;
        }
        float* dst = half ? g_eR : g_eL;
#pragma unroll
        for (int r = 0; r < NR; r++) dst[(row0 + r) * CZv + c2] = e[r];
    }
    __syncthreads();

    float h[NR];
#pragma unroll
    for (int r = 0; r < NR; r++) h[r] = b_n1[c];
    {
        const float4* W1r = (const float4*)(W_n1 + c * CSv);
#pragma unroll 4
        for (int q = 0; q < CSv / 4; q++) {
            float4 wv = W1r[q];
#pragma unroll
            for (int r = 0; r < NR; r++) {
                float4 xv = *(const float4*)&sx[r][q * 4];
                h[r] += xv.x * wv.x + xv.y * wv.y + xv.z * wv.z + xv.w * wv.w;
            }
        }
    }
    __syncthreads();
#pragma unroll
    for (int r = 0; r < NR; r++) sx[r][c] = fmaxf(h[r], 0.0f);
    __syncthreads();

    float o[NR];
#pragma unroll
    for (int r = 0; r < NR; r++) o[r] = b_n2[c];
    {
        const float4* W2r = (const float4*)(W_n2 + c * CSv);
#pragma unroll 4
        for (int q = 0; q < CSv / 4; q++) {
            float4 wv = W2r[q];
#pragma unroll
            for (int r = 0; r < NR; r++) {
                float4 xv = *(const float4*)&sx[r][q * 4];
                o[r] += xv.x * wv.x + xv.y * wv.y + xv.z * wv.z + xv.w * wv.w;
            }
        }
    }
    __syncthreads();
#pragma unroll
    for (int r = 0; r < NR; r++) sx[r][c] = o[r];
    __syncthreads();

    {
        const int w = tid >> 5, l = tid & 31;
        float v[8];
#pragma unroll
        for (int g = 0; g < 8; g++) v[g] = sx[w][g * 32 + l];
        float s = 0.0f;
#pragma unroll
        for (int g = 0; g < 8; g++) s += v[g];
#pragma unroll
        for (int off = 16; off > 0; off >>= 1) s += __shfl_xor_sync(0xffffffffu, s, off);
        float mean = s * (1.0f / 256.0f);
        float sq = 0.0f;
#pragma unroll
        for (int g = 0; g < 8; g++) { float d = v[g] - mean; sq += d * d; }
#pragma unroll
        for (int off = 16; off > 0; off >>= 1) sq += __shfl_xor_sync(0xffffffffu, sq, off);
        float rstd = rsqrtf(sq * (1.0f / 256.0f) + LN_EPS);
        const int row = row0 + w;
#pragma unroll
        for (int g = 0; g < 8; g++) {
            int cc = g * 32 + l;
            out_seq[row * CSv + cc] = (v[g] - mean) * rstd * g_n[cc] + be_n[cc];
        }
    }
}

// ---------------------------------------------------------------------------
// Edge kernel v3: warp-autonomous, single-fp16 X (H stays hi/lo in regs).
// Regions: Xh = X, then W2 (per-warp slices);  Ws = W1, then E0 park.
// W2 globals prefetched into registers before GEMM1.
// ---------------------------------------------------------------------------
#define WSTR 68
#define XH_W 0
#define WS_W (128 * WSTR)
#define REL_W (2 * 128 * WSTR)
#define EDGE_SMEM_U32 (REL_W + 128 + 8)
#define EDGE_SMEM_BYTES (EDGE_SMEM_U32 * 4)

__global__ __launch_bounds__(256, 2) void edge_kernel(
    const int* __restrict__ seq_idx,
    const float* __restrict__ b_e1, const float* __restrict__ b_e2,
    const float* __restrict__ g_e, const float* __restrict__ be_e,
    float* __restrict__ out_edge) {
    extern __shared__ uint32_t smw[];
    uint32_t* Xh = smw + XH_W;
    uint32_t* Ws = smw + WS_W;
    int* s_rel = (int*)(smw + REL_W);

    const int tid = threadIdx.x, w = tid >> 5, l = tid & 31;
    const int g = l >> 2, tig = l & 3;
    const int m0 = w * 16;
    const int bid = blockIdx.x;
    const int jt = bid % 3, i = (bid / 3) % NN, b = bid / (3 * NN);
    const int j0 = jt * 128;

    const uint32_t sb = smem_u32(smw);
    const int l16 = l & 15, lhi = l >> 4;
    const uint32_t aAddr = sb + ((m0 + l16) * WSTR + lhi * 4) * 4;       // X (Xh)
    const int nB = (l & 7) + (lhi << 3);
    const int kofB = ((l >> 3) & 1) << 2;
    const uint32_t bAddr1 = sb + (WS_W + nB * WSTR + kofB) * 4;          // W1 (Ws)
    const uint32_t bAddr2 = sb + (nB * WSTR + kofB) * 4;                 // W2 (Xh)

    if (tid < 128) {
        int rel = seq_idx[b * NN + i] - seq_idx[b * NN + j0 + tid] + 1000;
        s_rel[tid] = min(max(rel, 0), 2047);
    }
    {   // stage W1 into Ws (cooperative)
        const float4* Wsrc = (const float4*)g_W1f;
        for (int m = tid; m < 2048; m += 256) {
            int n = m >> 4, c4 = m & 15;
            *(float4*)&Ws[n * WSTR + c4 * 4] = Wsrc[m];
        }
    }
    __syncthreads();   // sync #1: rel + W1 visible

    // ---- X build (own 16 rows), single fp16 ----
    {
        const float4 Lv = ((const float4*)(g_eL + (size_t)(b * NN + i) * CZv))[l];
        unsigned long long* Xh64 = (unsigned long long*)Xh;
#pragma unroll 4
        for (int it = 0; it < 16; it++) {
            const int r = m0 + it;
            float4 tv = ((const float4*)(g_table + (size_t)s_rel[r] * CZv))[l];
            float4 rv = ((const float4*)(g_eR + (size_t)(b * NN + j0 + r) * CZv))[l];
            uint32_t h01 = packh2(fmaxf(tv.x + Lv.x + rv.x, 0.0f),
                                  fmaxf(tv.y + Lv.y + rv.y, 0.0f));
            uint32_t h23 = packh2(fmaxf(tv.z + Lv.z + rv.z, 0.0f),
                                  fmaxf(tv.w + Lv.w + rv.w, 0.0f));
            Xh64[r * 34 + l] = ((unsigned long long)h23 << 32) | h01;
        }
    }
    // Prefetch this warp's W2 slice into registers (hidden under GEMM1).
    float4 w2r[8];
    {
        const float4* Wsrc = (const float4*)g_W2f;
#pragma unroll
        for (int it = 0; it < 8; it++) {
            int idx = it * 32 + l;
            w2r[it] = Wsrc[(m0 + (idx >> 4)) * 16 + (idx & 15)];
        }
    }
    __syncwarp();

    // ---- GEMM1: acc1[16][4] = X(16 x k128, fp16) @ W1^T ----
    float acc1[16][4];
#pragma unroll
    for (int nt = 0; nt < 16; nt++)
#pragma unroll
        for (int e = 0; e < 4; e++) acc1[nt][e] = 0.0f;
#pragma unroll
    for (int kk = 0; kk < 8; kk++) {
        const uint32_t kb = kk * 32;
        uint32_t ah[4];
        ldsm_x4(ah[0], ah[1], ah[2], ah[3], aAddr + kb);
#pragma unroll
        for (int p = 0; p < 8; p++) {
            uint32_t bf[4];
            ldsm_x4(bf[0], bf[1], bf[2], bf[3], bAddr1 + p * (16 * WSTR * 4) + kb);
            mma16816(acc1[2 * p], ah[0], ah[1], ah[2], ah[3], bf[0], bf[1]);
            mma16816(acc1[2 * p + 1], ah[0], ah[1], ah[2], ah[3], bf[2], bf[3]);
        }
    }

    // ---- Transform: H = relu(acc1 + b_e1) -> A-fragments (hi/lo, identity) ----
    uint32_t Ah[8][4], Al[8][4];
#pragma unroll
    for (int q = 0; q < 8; q++) {
        const int c0 = 16 * q + 2 * tig;
        const int c1 = 16 * q + 8 + 2 * tig;
        float b00 = __ldg(b_e1 + c0), b01 = __ldg(b_e1 + c0 + 1);
        float b10 = __ldg(b_e1 + c1), b11 = __ldg(b_e1 + c1 + 1);
        float r0, r1, r2, r3, r4, r5, r6, r7;
        Ah[q][0] = packh_hi2(fmaxf(acc1[2 * q][0] + b00, 0.0f),
                             fmaxf(acc1[2 * q][1] + b01, 0.0f), r0, r1);
        Ah[q][1] = packh_hi2(fmaxf(acc1[2 * q][2] + b00, 0.0f),
                             fmaxf(acc1[2 * q][3] + b01, 0.0f), r2, r3);
        Ah[q][2] = packh_hi2(fmaxf(acc1[2 * q + 1][0] + b10, 0.0f),
                             fmaxf(acc1[2 * q + 1][1] + b11, 0.0f), r4, r5);
        Ah[q][3] = packh_hi2(fmaxf(acc1[2 * q + 1][2] + b10, 0.0f),
                             fmaxf(acc1[2 * q + 1][3] + b11, 0.0f), r6, r7);
        Al[q][0] = packh2(r0, r1);
        Al[q][1] = packh2(r2, r3);
        Al[q][2] = packh2(r4, r5);
        Al[q][3] = packh2(r6, r7);
    }

    // ---- Store prefetched W2 slice into OWN Xh rows (X dead for this warp) ----
    {
#pragma unroll
        for (int it = 0; it < 8; it++) {
            int idx = it * 32 + l;
            int rn = m0 + (idx >> 4), c4 = idx & 15;
            *(float4*)&Xh[rn * WSTR + c4 * 4] = w2r[it];
        }
    }
    __syncthreads();   // sync #2: all W2 slices staged

    // ---- GEMM2 in two 64-col halves (A = Ah/Al regs, B = W2 in Xh) ----
    float sumA = 0.0f, sqA = 0.0f, sumB = 0.0f, sqB = 0.0f;
    float* E0 = (float*)(Ws + m0 * WSTR);   // own W1 slice (dead): park half0
    const float* ge = g_e;
    const float* bee = be_e;

    float acc2[8][4];
#pragma unroll
    for (int h = 0; h < 2; h++) {
#pragma unroll
        for (int nt = 0; nt < 8; nt++)
#pragma unroll
            for (int e = 0; e < 4; e++) acc2[nt][e] = 0.0f;
#pragma unroll
        for (int kk = 0; kk < 8; kk++) {
            const uint32_t kb = kk * 32;
#pragma unroll
            for (int p = 0; p < 4; p++) {
                uint32_t bf[4];
                ldsm_x4(bf[0], bf[1], bf[2], bf[3],
                        bAddr2 + (h * 4 + p) * (16 * WSTR * 4) + kb);
                mma16816(acc2[2 * p], Al[kk][0], Al[kk][1], Al[kk][2], Al[kk][3],
                         bf[0], bf[1]);
                mma16816(acc2[2 * p], Ah[kk][0], Ah[kk][1], Ah[kk][2], Ah[kk][3],
                         bf[0], bf[1]);
                mma16816(acc2[2 * p + 1], Al[kk][0], Al[kk][1], Al[kk][2], Al[kk][3],
                         bf[2], bf[3]);
                mma16816(acc2[2 * p + 1], Ah[kk][0], Ah[kk][1], Ah[kk][2], Ah[kk][3],
                         bf[2], bf[3]);
            }
        }
#pragma unroll
        for (int nt = 0; nt < 8; nt++) {
            const int col = h * 64 + 8 * nt + 2 * tig;
            float bb0 = __ldg(b_e2 + col), bb1 = __ldg(b_e2 + col + 1);
            float v0 = acc2[nt][0] + bb0, v1 = acc2[nt][1] + bb1;
            float v2 = acc2[nt][2] + bb0, v3 = acc2[nt][3] + bb1;
            sumA += v0 + v1; sqA += v0 * v0 + v1 * v1;
            sumB += v2 + v3; sqB += v2 * v2 + v3 * v3;
            if (h == 0) {
                *(float2*)&E0[g * WSTR + 8 * nt + 2 * tig] = make_float2(v0, v1);
                *(float2*)&E0[(g + 8) * WSTR + 8 * nt + 2 * tig] = make_float2(v2, v3);
            } else {
                acc2[nt][0] = v0; acc2[nt][1] = v1;
                acc2[nt][2] = v2; acc2[nt][3] = v3;
            }
        }
    }

    // ---- LN stats over the 4-lane quad ----
#pragma unroll
    for (int off = 1; off <= 2; off <<= 1) {
        sumA += __shfl_xor_sync(0xffffffffu, sumA, off);
        sqA += __shfl_xor_sync(0xffffffffu, sqA, off);
        sumB += __shfl_xor_sync(0xffffffffu, sumB, off);
        sqB += __shfl_xor_sync(0xffffffffu, sqB, off);
    }
    const float mA = sumA * (1.0f / 128.0f);
    const float rA = rsqrtf(fmaxf(sqA * (1.0f / 128.0f) - mA * mA, 0.0f) + LN_EPS);
    const float mB = sumB * (1.0f / 128.0f);
    const float rB = rsqrtf(fmaxf(sqB * (1.0f / 128.0f) - mB * mB, 0.0f) + LN_EPS);

    const size_t rowbase = ((size_t)(b * NN + i) * NN + (j0 + m0));

    // half1 (cols 64..127) directly from registers
    {
        float* dstg = out_edge + (rowbase + g) * CZv;
        float* dstg8 = out_edge + (rowbase + g + 8) * CZv;
#pragma unroll
        for (int nt = 0; nt < 8; nt++) {
            const int col = 64 + 8 * nt + 2 * tig;
            float ge0 = __ldg(ge + col), ge1 = __ldg(ge + col + 1);
            float be0 = __ldg(bee + col), be1 = __ldg(bee + col + 1);
            *(float2*)&dstg[col] = make_float2(
                (acc2[nt][0] - mA) * rA * ge0 + be0,
                (acc2[nt][1] - mA) * rA * ge1 + be1);
            *(float2*)&dstg8[col] = make_float2(
                (acc2[nt][2] - mB) * rB * ge0 + be0,
                (acc2[nt][3] - mB) * rB * ge1 + be1);
        }
    }
    __syncwarp();

    // half0 (cols 0..63) coalesced from E0 with shuffled stats
    {
        const float ge0 = ge[l], ge1 = ge[32 + l];
        const float be0 = bee[l], be1 = bee[32 + l];
#pragma unroll 2
        for (int r = 0; r < 16; r++) {
            const int src = 4 * (r & 7);
            float m1 = __shfl_sync(0xffffffffu, mA, src);
            float m2 = __shfl_sync(0xffffffffu, mB, src);
            float r1 = __shfl_sync(0xffffffffu, rA, src);
            float r2 = __shfl_sync(0xffffffffu, rB, src);
            float mean = (r < 8) ? m1 : m2;
            float rstd = (r < 8) ? r1 : r2;
            float v0 = E0[r * WSTR + l];
            float v1 = E0[r * WSTR + 32 + l];
            float* dst = out_edge + (rowbase + r) * CZv;
            dst[l] = (v0 - mean) * rstd * ge0 + be0;
            dst[32 + l] = (v1 - mean) * rstd * ge1 + be1;
        }
    }
}

// ===========================================================================
extern "C" void kernel_launch(void* const* d_in, const int* in_sizes, int n_in,
                              void* d_out, int out_size) {
    const int* seq_idx = (const int*)d_in[0];
    const float* seq_feat = (const float*)d_in[1];
    const float* timestep = (const float*)d_in[2];
    const float* frame_mask = (const float*)d_in[3];
    const float* W_npos = (const float*)d_in[4];
    const float* b_npos = (const float*)d_in[5];
    const float* W_ntf = (const float*)d_in[6];
    const float* b_ntf = (const float*)d_in[7];
    const float* W_ntime = (const float*)d_in[8];
    const float* b_ntime = (const float*)d_in[9];
    const float* W_n1 = (const float*)d_in[10];
    const float* b_n1 = (const float*)d_in[11];
    const float* W_n2 = (const float*)d_in[12];
    const float* b_n2 = (const float*)d_in[13];
    const float* g_n = (const float*)d_in[14];
    const float* be_n = (const float*)d_in[15];
    const float* W_epos = (const float*)d_in[16];
    const float* b_epos = (const float*)d_in[17];
    const float* W_etf = (const float*)d_in[18];
    const float* b_etf = (const float*)d_in[19];
    const float* W_etime = (const float*)d_in[20];
    const float* b_etime = (const float*)d_in[21];
    const float* W_e1 = (const float*)d_in[22];
    const float* b_e1 = (const float*)d_in[23];
    const float* W_e2 = (const float*)d_in[24];
    const float* b_e2 = (const float*)d_in[25];
    const float* g_e = (const float*)d_in[26];
    const float* be_e = (const float*)d_in[27];

    float* out = (float*)d_out;
    float* out_seq = out;
    float* out_edge = out + NB * NN * CSv;

    static int configured = 0;
    if (!configured) {
        cudaFuncSetAttribute(edge_kernel, cudaFuncAttributeMaxDynamicSharedMemorySize,
                             EDGE_SMEM_BYTES);
        configured = 1;
    }

    setup_kernel<<<TBLK + NODEB + 64, 256>>>(
        seq_idx, seq_feat, timestep, frame_mask,
        W_npos, b_npos, W_ntf, b_ntf, W_ntime, b_ntime,
        W_n1, b_n1, W_n2, b_n2, g_n, be_n,
        W_epos, b_epos, b_etf, b_etime, W_etf, W_etime,
        W_e1, W_e2, out_seq);
    edge_kernel<<<NB * NN * 3, 256, EDGE_SMEM_BYTES>>>(seq_idx, b_e1, b_e2,
                                                       g_e, be_e, out_edge);
}